// round 4
// baseline (speedup 1.0000x reference)
#include <cuda_runtime.h>
#include <cuda_bf16.h>
#include <math.h>

// Problem dims (fixed by the reference)
#define BATCH 256
#define NPIX  196
#define CDIM  2048
#define ADIM  512
#define LDIM  512
#define MTOT  (BATCH * NPIX)   // 50176 = 392 * 128

// GEMM tiling
#define BM 128
#define BN 128
#define BK 16
#define NBLK (ADIM / BN)       // 4

// Scratch (device globals — no allocation allowed)
__device__ float g_att2[BATCH * ADIM];        // (B, A)
__device__ float g_att_part[NBLK * MTOT];     // per-N-block partial scores
__device__ float g_alpha[MTOT];               // softmax weights

// ---------------------------------------------------------------------------
// K1: att2[b][a] = lstm[b] . Wl[a] + bl[a]
// 512 threads per block, 8 batches per block (32 blocks).
// ---------------------------------------------------------------------------
__global__ void att2_kernel(const float* __restrict__ lstm,
                            const float* __restrict__ Wl,
                            const float* __restrict__ bl,
                            float* __restrict__ att2) {
    __shared__ float h[8][LDIM];
    const int b0 = blockIdx.x * 8;
    const int a = threadIdx.x;   // 0..511

    #pragma unroll
    for (int i = 0; i < 8; i++)
        h[i][a] = lstm[(b0 + i) * LDIM + a];
    __syncthreads();

    const float4* w4 = reinterpret_cast<const float4*>(Wl + (size_t)a * LDIM);
    float acc[8] = {0.f, 0.f, 0.f, 0.f, 0.f, 0.f, 0.f, 0.f};
    #pragma unroll 4
    for (int l4 = 0; l4 < LDIM / 4; l4++) {
        float4 wv = w4[l4];
        int l = l4 * 4;
        #pragma unroll
        for (int i = 0; i < 8; i++) {
            acc[i] += h[i][l + 0] * wv.x;
            acc[i] += h[i][l + 1] * wv.y;
            acc[i] += h[i][l + 2] * wv.z;
            acc[i] += h[i][l + 3] * wv.w;
        }
    }
    const float bv = bl[a];
    #pragma unroll
    for (int i = 0; i < 8; i++)
        att2[(b0 + i) * ADIM + a] = acc[i] + bv;
}

// ---------------------------------------------------------------------------
// K2: fused score GEMM.
//   C[m][n] = conv[m] . Wc[n]   (m in 0..50175, n in 0..511)
//   partial[bn][m] = sum_{n in bn-block} relu(C[m][n] + bc[n] + att2[b][n]) * Wf[n]
// 128x128x16 tile, 256 threads, 8x8 per thread, fp32.
// ---------------------------------------------------------------------------
__global__ __launch_bounds__(256, 2)
void score_gemm_kernel(const float* __restrict__ A,    // conv_out, M x K
                       const float* __restrict__ Wc,   // N x K
                       const float* __restrict__ bc,
                       const float* __restrict__ Wf,   // (1, 512)
                       const float* __restrict__ att2, // B x 512
                       float* __restrict__ att_part)   // NBLK x M
{
    __shared__ float As[BK][BM + 4];
    __shared__ float Bs[BK][BN + 4];

    const int bm = blockIdx.x;             // 0..391
    const int bn = blockIdx.y;             // 0..3
    const int tid = threadIdx.x;           // 0..255
    const int tx = tid & 15;
    const int ty = tid >> 4;

    float acc[8][8];
    #pragma unroll
    for (int i = 0; i < 8; i++)
        #pragma unroll
        for (int j = 0; j < 8; j++) acc[i][j] = 0.f;

    const float* Ab = A  + (size_t)bm * BM * CDIM;
    const float* Bb = Wc + (size_t)bn * BN * CDIM;

    const int l_row  = tid >> 2;   // 0..63
    const int l_col4 = tid & 3;    // 0..3  (float4 index within 16-wide row)

    for (int k0 = 0; k0 < CDIM; k0 += BK) {
        #pragma unroll
        for (int i = 0; i < 2; i++) {
            const int r = l_row + i * 64;
            float4 v = *reinterpret_cast<const float4*>(Ab + (size_t)r * CDIM + k0 + l_col4 * 4);
            As[l_col4 * 4 + 0][r] = v.x;
            As[l_col4 * 4 + 1][r] = v.y;
            As[l_col4 * 4 + 2][r] = v.z;
            As[l_col4 * 4 + 3][r] = v.w;
            float4 w = *reinterpret_cast<const float4*>(Bb + (size_t)r * CDIM + k0 + l_col4 * 4);
            Bs[l_col4 * 4 + 0][r] = w.x;
            Bs[l_col4 * 4 + 1][r] = w.y;
            Bs[l_col4 * 4 + 2][r] = w.z;
            Bs[l_col4 * 4 + 3][r] = w.w;
        }
        __syncthreads();

        #pragma unroll
        for (int kk = 0; kk < BK; kk++) {
            float4 a0 = *reinterpret_cast<const float4*>(&As[kk][ty * 8]);
            float4 a1 = *reinterpret_cast<const float4*>(&As[kk][ty * 8 + 4]);
            float4 b0 = *reinterpret_cast<const float4*>(&Bs[kk][tx * 8]);
            float4 b1 = *reinterpret_cast<const float4*>(&Bs[kk][tx * 8 + 4]);
            float af[8] = {a0.x, a0.y, a0.z, a0.w, a1.x, a1.y, a1.z, a1.w};
            float bfr[8] = {b0.x, b0.y, b0.z, b0.w, b1.x, b1.y, b1.z, b1.w};
            #pragma unroll
            for (int i = 0; i < 8; i++)
                #pragma unroll
                for (int j = 0; j < 8; j++)
                    acc[i][j] += af[i] * bfr[j];
        }
        __syncthreads();
    }

    // Epilogue: relu(acc + bc + att2) . Wf, reduced per row (deterministic).
    float wf[8], bcv[8];
    #pragma unroll
    for (int j = 0; j < 8; j++) {
        const int n = bn * BN + tx * 8 + j;
        wf[j]  = Wf[n];
        bcv[j] = bc[n];
    }

    __shared__ float red[BM][17];   // [row][tx], padded
    #pragma unroll
    for (int i = 0; i < 8; i++) {
        const int m = bm * BM + ty * 8 + i;
        const int b = m / NPIX;
        const float* a2 = att2 + (size_t)b * ADIM + bn * BN + tx * 8;
        float s = 0.f;
        #pragma unroll
        for (int j = 0; j < 8; j++) {
            float v = acc[i][j] + bcv[j] + a2[j];
            v = fmaxf(v, 0.f) * wf[j];
            s += v;
        }
        red[ty * 8 + i][tx] = s;
    }
    __syncthreads();

    if (tid < BM) {
        float s = 0.f;
        #pragma unroll
        for (int t = 0; t < 16; t++) s += red[tid][t];
        att_part[(size_t)bn * MTOT + bm * BM + tid] = s;
    }
}

// ---------------------------------------------------------------------------
// K3: softmax over P=196 per batch row.
// ---------------------------------------------------------------------------
__global__ void softmax_kernel(const float* __restrict__ att_part,
                               const float* __restrict__ bf,
                               float* __restrict__ alpha) {
    __shared__ float sv[256];
    const int b = blockIdx.x;
    const int tid = threadIdx.x;

    float val = 0.f;
    float v = -INFINITY;
    if (tid < NPIX) {
        const int m = b * NPIX + tid;
        val = bf[0]
            + att_part[0 * MTOT + m]
            + att_part[1 * MTOT + m]
            + att_part[2 * MTOT + m]
            + att_part[3 * MTOT + m];
        v = val;
    }
    sv[tid] = v;
    __syncthreads();
    #pragma unroll
    for (int s = 128; s > 0; s >>= 1) {
        if (tid < s) sv[tid] = fmaxf(sv[tid], sv[tid + s]);
        __syncthreads();
    }
    const float mx = sv[0];
    __syncthreads();

    const float e = (tid < NPIX) ? expf(val - mx) : 0.f;
    sv[tid] = e;
    __syncthreads();
    #pragma unroll
    for (int s = 128; s > 0; s >>= 1) {
        if (tid < s) sv[tid] = sv[tid] + sv[tid + s];
        __syncthreads();
    }
    const float sum = sv[0];
    if (tid < NPIX) alpha[b * NPIX + tid] = e / sum;
}

// ---------------------------------------------------------------------------
// K4: out[b][c] = sum_p conv[b][p][c] * alpha[b][p]   (memory bound)
// ---------------------------------------------------------------------------
__global__ void pool_kernel(const float* __restrict__ conv,
                            const float* __restrict__ alpha,
                            float* __restrict__ out) {
    __shared__ float al[NPIX];
    const int b = blockIdx.y;
    const int c = blockIdx.x * 256 + threadIdx.x;
    if (threadIdx.x < NPIX) al[threadIdx.x] = alpha[b * NPIX + threadIdx.x];
    __syncthreads();

    const float* cp = conv + (size_t)b * NPIX * CDIM + c;
    float acc = 0.f;
    #pragma unroll 4
    for (int p = 0; p < NPIX; p++)
        acc += cp[(size_t)p * CDIM] * al[p];
    out[(size_t)b * CDIM + c] = acc;
}

// ---------------------------------------------------------------------------
extern "C" void kernel_launch(void* const* d_in, const int* in_sizes, int n_in,
                              void* d_out, int out_size) {
    const float* conv = (const float*)d_in[0];
    const float* lstm = (const float*)d_in[1];
    const float* Wc   = (const float*)d_in[2];
    const float* bc   = (const float*)d_in[3];
    const float* Wl   = (const float*)d_in[4];
    const float* bl   = (const float*)d_in[5];
    const float* Wf   = (const float*)d_in[6];
    const float* bf   = (const float*)d_in[7];
    float* out = (float*)d_out;

    float* att2;     cudaGetSymbolAddress((void**)&att2, g_att2);
    float* att_part; cudaGetSymbolAddress((void**)&att_part, g_att_part);
    float* alpha;    cudaGetSymbolAddress((void**)&alpha, g_alpha);

    att2_kernel<<<BATCH / 8, LDIM>>>(lstm, Wl, bl, att2);

    dim3 gg(MTOT / BM, NBLK);
    score_gemm_kernel<<<gg, 256>>>(conv, Wc, bc, Wf, att2, att_part);

    softmax_kernel<<<BATCH, 256>>>(att_part, bf, alpha);

    pool_kernel<<<dim3(CDIM / 256, BATCH), 256>>>(conv, alpha, out);
}

// round 6
// speedup vs baseline: 2.2387x; 2.2387x over previous
#include <cuda_runtime.h>
#include <cuda_bf16.h>
#include <math.h>
#include <stdint.h>

// Problem dims (fixed by the reference)
#define BATCH 256
#define NPIX  196
#define CDIM  2048
#define ADIM  512
#define LDIM  512
#define MTOT  (BATCH * NPIX)   // 50176 = 392 * 128

// GEMM tiling (mma.sync m16n8k16)
#define BM 128
#define BN 256
#define BK 16
#define NBLK (ADIM / BN)       // 2
#define NITER (CDIM / BK)      // 128
#define WM 64                  // warp tile m
#define WN 64                  // warp tile n

// Scratch (device globals — no allocation allowed)
__device__ float g_att2[BATCH * ADIM];
__device__ float g_att_part[NBLK * MTOT];
__device__ float g_alpha[MTOT];
__device__ __nv_bfloat16 g_Wc_hi[ADIM * CDIM];
__device__ __nv_bfloat16 g_Wc_lo[ADIM * CDIM];

// smem: row stride 48B (16 bf16 + 8 pad) — conflict-free LDSM, 16B aligned
#define ROWB 48
#define SM_A_HI(b) ((b) * 36864 + 0)
#define SM_A_LO(b) ((b) * 36864 + 6144)
#define SM_B_HI(b) ((b) * 36864 + 12288)
#define SM_B_LO(b) ((b) * 36864 + 24576)
#define SMEM_BYTES (2 * 36864)

__device__ __forceinline__ uint32_t smem_to_u32(const void* p) {
    uint32_t a;
    asm("{ .reg .u64 t; cvta.to.shared.u64 t, %1; cvt.u32.u64 %0, t; }" : "=r"(a) : "l"(p));
    return a;
}
__device__ __forceinline__ void ldsm4(uint32_t* r, uint32_t addr) {
    asm volatile("ldmatrix.sync.aligned.m8n8.x4.shared.b16 {%0,%1,%2,%3}, [%4];"
                 : "=r"(r[0]), "=r"(r[1]), "=r"(r[2]), "=r"(r[3]) : "r"(addr));
}
__device__ __forceinline__ void mma16816(float* c, const uint32_t* a, const uint32_t* b) {
    asm volatile("mma.sync.aligned.m16n8k16.row.col.f32.bf16.bf16.f32 "
                 "{%0,%1,%2,%3}, {%4,%5,%6,%7}, {%8,%9}, {%0,%1,%2,%3};"
                 : "+f"(c[0]), "+f"(c[1]), "+f"(c[2]), "+f"(c[3])
                 : "r"(a[0]), "r"(a[1]), "r"(a[2]), "r"(a[3]), "r"(b[0]), "r"(b[1]));
}
__device__ __forceinline__ uint32_t pack_bf16(__nv_bfloat16 a, __nv_bfloat16 b) {
    return (uint32_t)__bfloat16_as_ushort(a) | ((uint32_t)__bfloat16_as_ushort(b) << 16);
}

// ---------------------------------------------------------------------------
// K0: convert Wc -> bf16 hi/lo split (1M elements, once per launch)
// ---------------------------------------------------------------------------
__global__ void convert_wc_kernel(const float* __restrict__ Wc) {
    const int i4 = blockIdx.x * 256 + threadIdx.x;
    float4 v = reinterpret_cast<const float4*>(Wc)[i4];
    __nv_bfloat16 h0 = __float2bfloat16(v.x), h1 = __float2bfloat16(v.y);
    __nv_bfloat16 h2 = __float2bfloat16(v.z), h3 = __float2bfloat16(v.w);
    __nv_bfloat16 l0 = __float2bfloat16(v.x - __bfloat162float(h0));
    __nv_bfloat16 l1 = __float2bfloat16(v.y - __bfloat162float(h1));
    __nv_bfloat16 l2 = __float2bfloat16(v.z - __bfloat162float(h2));
    __nv_bfloat16 l3 = __float2bfloat16(v.w - __bfloat162float(h3));
    reinterpret_cast<uint2*>(g_Wc_hi)[i4] = make_uint2(pack_bf16(h0, h1), pack_bf16(h2, h3));
    reinterpret_cast<uint2*>(g_Wc_lo)[i4] = make_uint2(pack_bf16(l0, l1), pack_bf16(l2, l3));
}

// ---------------------------------------------------------------------------
// K1: att2[b][a] = lstm[b] . Wl[a] + bl[a]
// ---------------------------------------------------------------------------
__global__ void att2_kernel(const float* __restrict__ lstm,
                            const float* __restrict__ Wl,
                            const float* __restrict__ bl,
                            float* __restrict__ att2) {
    __shared__ float h[8][LDIM];
    const int b0 = blockIdx.x * 8;
    const int a = threadIdx.x;
    #pragma unroll
    for (int i = 0; i < 8; i++) h[i][a] = lstm[(b0 + i) * LDIM + a];
    __syncthreads();
    const float4* w4 = reinterpret_cast<const float4*>(Wl + (size_t)a * LDIM);
    float acc[8] = {0.f, 0.f, 0.f, 0.f, 0.f, 0.f, 0.f, 0.f};
    #pragma unroll 4
    for (int l4 = 0; l4 < LDIM / 4; l4++) {
        float4 wv = w4[l4];
        int l = l4 * 4;
        #pragma unroll
        for (int i = 0; i < 8; i++) {
            acc[i] += h[i][l + 0] * wv.x;
            acc[i] += h[i][l + 1] * wv.y;
            acc[i] += h[i][l + 2] * wv.z;
            acc[i] += h[i][l + 3] * wv.w;
        }
    }
    const float bv = bl[a];
    #pragma unroll
    for (int i = 0; i < 8; i++) att2[(b0 + i) * ADIM + a] = acc[i] + bv;
}

// ---------------------------------------------------------------------------
// K2: bf16-split-3 score GEMM on mma.sync + fused relu/Wf epilogue.
// Grid (392, 2), 256 threads (8 warps, 2x4), warp tile 64x64.
// ---------------------------------------------------------------------------
__global__ void __launch_bounds__(256, 1)
score_gemm_kernel(const float* __restrict__ A,      // conv_out, M x K
                  const float* __restrict__ bc,
                  const float* __restrict__ Wf,
                  const float* __restrict__ att2,   // B x 512
                  float* __restrict__ att_part)     // NBLK x M
{
    extern __shared__ char sm[];
    const uint32_t sb = smem_to_u32(sm);
    const int tid = threadIdx.x;
    const int lane = tid & 31;
    const int wid = tid >> 5;
    const int warp_m = wid >> 2;       // 0..1
    const int warp_n = wid & 3;        // 0..3
    const int bm = blockIdx.x;
    const int bn = blockIdx.y;
    const float* Ab = A + (size_t)bm * BM * CDIM;

    // ldmatrix per-lane offsets
    uint32_t aoff[4], boff[4];
    {
        const int ar = lane & 15, abyte = (lane >> 4) * 16;
        #pragma unroll
        for (int mb = 0; mb < 4; mb++)
            aoff[mb] = (uint32_t)((warp_m * WM + mb * 16 + ar) * ROWB + abyte);
        const int bnr = (lane & 7) + ((lane >> 4) << 3);
        const int bbyte = ((lane >> 3) & 1) * 16;
        #pragma unroll
        for (int g = 0; g < 4; g++)
            boff[g] = (uint32_t)((warp_n * WN + g * 16 + bnr) * ROWB + bbyte);
    }

    // global load/store index helpers (2 chunks per thread per matrix)
    // A: idx = tid + 256*i -> row = idx>>2 (0..127), c4 = idx&3
    // B: idx = tid + 256*i -> row = idx>>1 (0..255), q = idx&1
    float4 ga[2];
    uint4 gbh[2], gbl[2];

    const uint4* WcHi4 = reinterpret_cast<const uint4*>(g_Wc_hi);
    const uint4* WcLo4 = reinterpret_cast<const uint4*>(g_Wc_lo);

    float acc[4][8][4];
    #pragma unroll
    for (int mb = 0; mb < 4; mb++)
        #pragma unroll
        for (int nb = 0; nb < 8; nb++)
            #pragma unroll
            for (int j = 0; j < 4; j++) acc[mb][nb][j] = 0.f;

    // ---- load chunk 0 into regs ----
    #pragma unroll
    for (int i = 0; i < 2; i++) {
        const int ia = tid + 256 * i;
        ga[i] = *reinterpret_cast<const float4*>(Ab + (size_t)(ia >> 2) * CDIM + (ia & 3) * 4);
        const int ib = tid + 256 * i;
        const size_t gidx = (((size_t)(bn * BN + (ib >> 1)) * CDIM) >> 3) + (ib & 1);
        gbh[i] = WcHi4[gidx];
        gbl[i] = WcLo4[gidx];
    }
    // ---- store chunk 0 to smem buf 0 ----
    #pragma unroll
    for (int i = 0; i < 2; i++) {
        const int ia = tid + 256 * i;
        const int row = ia >> 2, c4 = ia & 3;
        float4 v = ga[i];
        __nv_bfloat16 h0 = __float2bfloat16(v.x), h1 = __float2bfloat16(v.y);
        __nv_bfloat16 h2 = __float2bfloat16(v.z), h3 = __float2bfloat16(v.w);
        __nv_bfloat16 l0 = __float2bfloat16(v.x - __bfloat162float(h0));
        __nv_bfloat16 l1 = __float2bfloat16(v.y - __bfloat162float(h1));
        __nv_bfloat16 l2 = __float2bfloat16(v.z - __bfloat162float(h2));
        __nv_bfloat16 l3 = __float2bfloat16(v.w - __bfloat162float(h3));
        const int off = row * ROWB + c4 * 8;
        *reinterpret_cast<uint2*>(sm + SM_A_HI(0) + off) = make_uint2(pack_bf16(h0, h1), pack_bf16(h2, h3));
        *reinterpret_cast<uint2*>(sm + SM_A_LO(0) + off) = make_uint2(pack_bf16(l0, l1), pack_bf16(l2, l3));
        const int rowb = ia >> 1, q = ia & 1;
        const int offb = rowb * ROWB + q * 16;
        *reinterpret_cast<uint4*>(sm + SM_B_HI(0) + offb) = gbh[i];
        *reinterpret_cast<uint4*>(sm + SM_B_LO(0) + offb) = gbl[i];
    }
    __syncthreads();

    #pragma unroll 1
    for (int it = 0; it < NITER; it++) {
        const int buf = it & 1;
        const int k0 = (it + 1) * BK;
        // prefetch next chunk into regs
        if (it + 1 < NITER) {
            #pragma unroll
            for (int i = 0; i < 2; i++) {
                const int ia = tid + 256 * i;
                ga[i] = *reinterpret_cast<const float4*>(Ab + (size_t)(ia >> 2) * CDIM + k0 + (ia & 3) * 4);
                const size_t gidx = (((size_t)(bn * BN + (ia >> 1)) * CDIM + k0) >> 3) + (ia & 1);
                gbh[i] = WcHi4[gidx];
                gbl[i] = WcLo4[gidx];
            }
        }

        // ---- compute on buf ----
        uint32_t ah[4][4], al[4][4], bb[4][4];
        #pragma unroll
        for (int mb = 0; mb < 4; mb++) ldsm4(ah[mb], sb + SM_A_HI(buf) + aoff[mb]);
        #pragma unroll
        for (int mb = 0; mb < 4; mb++) ldsm4(al[mb], sb + SM_A_LO(buf) + aoff[mb]);
        #pragma unroll
        for (int g = 0; g < 4; g++) ldsm4(bb[g], sb + SM_B_HI(buf) + boff[g]);
        #pragma unroll
        for (int mb = 0; mb < 4; mb++)
            #pragma unroll
            for (int nb = 0; nb < 8; nb++)
                mma16816(acc[mb][nb], ah[mb], &bb[nb >> 1][(nb & 1) * 2]);
        #pragma unroll
        for (int mb = 0; mb < 4; mb++)
            #pragma unroll
            for (int nb = 0; nb < 8; nb++)
                mma16816(acc[mb][nb], al[mb], &bb[nb >> 1][(nb & 1) * 2]);
        #pragma unroll
        for (int g = 0; g < 4; g++) ldsm4(bb[g], sb + SM_B_LO(buf) + boff[g]);
        #pragma unroll
        for (int mb = 0; mb < 4; mb++)
            #pragma unroll
            for (int nb = 0; nb < 8; nb++)
                mma16816(acc[mb][nb], ah[mb], &bb[nb >> 1][(nb & 1) * 2]);

        // ---- store next chunk to other buffer ----
        if (it + 1 < NITER) {
            const int nbf = buf ^ 1;
            #pragma unroll
            for (int i = 0; i < 2; i++) {
                const int ia = tid + 256 * i;
                const int row = ia >> 2, c4 = ia & 3;
                float4 v = ga[i];
                __nv_bfloat16 h0 = __float2bfloat16(v.x), h1 = __float2bfloat16(v.y);
                __nv_bfloat16 h2 = __float2bfloat16(v.z), h3 = __float2bfloat16(v.w);
                __nv_bfloat16 l0 = __float2bfloat16(v.x - __bfloat162float(h0));
                __nv_bfloat16 l1 = __float2bfloat16(v.y - __bfloat162float(h1));
                __nv_bfloat16 l2 = __float2bfloat16(v.z - __bfloat162float(h2));
                __nv_bfloat16 l3 = __float2bfloat16(v.w - __bfloat162float(h3));
                const int off = row * ROWB + c4 * 8;
                *reinterpret_cast<uint2*>(sm + SM_A_HI(nbf) + off) = make_uint2(pack_bf16(h0, h1), pack_bf16(h2, h3));
                *reinterpret_cast<uint2*>(sm + SM_A_LO(nbf) + off) = make_uint2(pack_bf16(l0, l1), pack_bf16(l2, l3));
                const int rowb = ia >> 1, q = ia & 1;
                const int offb = rowb * ROWB + q * 16;
                *reinterpret_cast<uint4*>(sm + SM_B_HI(nbf) + offb) = gbh[i];
                *reinterpret_cast<uint4*>(sm + SM_B_LO(nbf) + offb) = gbl[i];
            }
        }
        __syncthreads();
    }

    // ---- epilogue: relu(C + bc + att2) . Wf reduced over n ----
    // preload Wf/bc for this thread's 16 columns
    float wfv[16], bcv[16];
    const int ncol0 = bn * BN + warp_n * WN;
    #pragma unroll
    for (int nb = 0; nb < 8; nb++)
        #pragma unroll
        for (int jj = 0; jj < 2; jj++) {
            const int n = ncol0 + nb * 8 + 2 * (lane & 3) + jj;
            wfv[nb * 2 + jj] = Wf[n];
            bcv[nb * 2 + jj] = bc[n];
        }

    float* red = reinterpret_cast<float*>(sm);   // [4][128]
    #pragma unroll
    for (int mb = 0; mb < 4; mb++) {
        #pragma unroll
        for (int half = 0; half < 2; half++) {
            const int m_loc = warp_m * WM + mb * 16 + (lane >> 2) + half * 8;
            const int m = bm * BM + m_loc;
            const int b = m / NPIX;
            const float* a2 = att2 + (size_t)b * ADIM + ncol0;
            float s = 0.f;
            #pragma unroll
            for (int nb = 0; nb < 8; nb++)
                #pragma unroll
                for (int jj = 0; jj < 2; jj++) {
                    const int ci = half * 2 + jj;
                    const int nrel = nb * 8 + 2 * (lane & 3) + jj;
                    float v = acc[mb][nb][ci] + bcv[nb * 2 + jj] + a2[nrel];
                    s += fmaxf(v, 0.f) * wfv[nb * 2 + jj];
                }
            s += __shfl_xor_sync(0xFFFFFFFF, s, 1);
            s += __shfl_xor_sync(0xFFFFFFFF, s, 2);
            if ((lane & 3) == 0) red[warp_n * BM + m_loc] = s;
        }
    }
    __syncthreads();
    if (tid < BM) {
        float s = red[0 * BM + tid] + red[1 * BM + tid] + red[2 * BM + tid] + red[3 * BM + tid];
        att_part[(size_t)bn * MTOT + bm * BM + tid] = s;
    }
}

// ---------------------------------------------------------------------------
// K3: softmax over P=196 per batch row (2 partials).
// ---------------------------------------------------------------------------
__global__ void softmax_kernel(const float* __restrict__ att_part,
                               const float* __restrict__ bf,
                               float* __restrict__ alpha) {
    __shared__ float sv[256];
    const int b = blockIdx.x;
    const int tid = threadIdx.x;
    float val = 0.f;
    float v = -INFINITY;
    if (tid < NPIX) {
        const int m = b * NPIX + tid;
        val = bf[0] + att_part[0 * MTOT + m] + att_part[1 * MTOT + m];
        v = val;
    }
    sv[tid] = v;
    __syncthreads();
    #pragma unroll
    for (int s = 128; s > 0; s >>= 1) {
        if (tid < s) sv[tid] = fmaxf(sv[tid], sv[tid + s]);
        __syncthreads();
    }
    const float mx = sv[0];
    __syncthreads();
    const float e = (tid < NPIX) ? expf(val - mx) : 0.f;
    sv[tid] = e;
    __syncthreads();
    #pragma unroll
    for (int s = 128; s > 0; s >>= 1) {
        if (tid < s) sv[tid] = sv[tid] + sv[tid + s];
        __syncthreads();
    }
    const float sum = sv[0];
    if (tid < NPIX) alpha[b * NPIX + tid] = e / sum;
}

// ---------------------------------------------------------------------------
// K4: out[b][c] = sum_p conv[b][p][c] * alpha[b][p]   (float4 vectorized)
// ---------------------------------------------------------------------------
__global__ void pool_kernel(const float* __restrict__ conv,
                            const float* __restrict__ alpha,
                            float* __restrict__ out) {
    __shared__ float al[NPIX];
    const int b = blockIdx.y;
    const int c4 = blockIdx.x * 256 + threadIdx.x;
    if (threadIdx.x < NPIX) al[threadIdx.x] = alpha[b * NPIX + threadIdx.x];
    __syncthreads();
    const float4* cp = reinterpret_cast<const float4*>(conv + (size_t)b * NPIX * CDIM) + c4;
    float4 acc = make_float4(0.f, 0.f, 0.f, 0.f);
    #pragma unroll 4
    for (int p = 0; p < NPIX; p++) {
        float4 v = cp[(size_t)p * (CDIM / 4)];
        float a = al[p];
        acc.x += v.x * a; acc.y += v.y * a; acc.z += v.z * a; acc.w += v.w * a;
    }
    reinterpret_cast<float4*>(out)[(size_t)b * (CDIM / 4) + c4] = acc;
}

// ---------------------------------------------------------------------------
extern "C" void kernel_launch(void* const* d_in, const int* in_sizes, int n_in,
                              void* d_out, int out_size) {
    const float* conv = (const float*)d_in[0];
    const float* lstm = (const float*)d_in[1];
    const float* Wc   = (const float*)d_in[2];
    const float* bc   = (const float*)d_in[3];
    const float* Wl   = (const float*)d_in[4];
    const float* bl   = (const float*)d_in[5];
    const float* Wf   = (const float*)d_in[6];
    const float* bf   = (const float*)d_in[7];
    float* out = (float*)d_out;

    float* att2;     cudaGetSymbolAddress((void**)&att2, g_att2);
    float* att_part; cudaGetSymbolAddress((void**)&att_part, g_att_part);
    float* alpha;    cudaGetSymbolAddress((void**)&alpha, g_alpha);

    cudaFuncSetAttribute(score_gemm_kernel,
                         cudaFuncAttributeMaxDynamicSharedMemorySize, SMEM_BYTES);

    convert_wc_kernel<<<(ADIM * CDIM / 4) / 256, 256>>>(Wc);
    att2_kernel<<<BATCH / 8, LDIM>>>(lstm, Wl, bl, att2);

    dim3 gg(MTOT / BM, NBLK);
    score_gemm_kernel<<<gg, 256, SMEM_BYTES>>>(conv, bc, Wf, att2, att_part);

    softmax_kernel<<<BATCH, 256>>>(att_part, bf, alpha);
    pool_kernel<<<dim3(CDIM / 4 / 256, BATCH), 256>>>(conv, alpha, out);
}